// round 5
// baseline (speedup 1.0000x reference)
#include <cuda_runtime.h>
#include <cuda_bf16.h>
#include <math.h>
#include <stdint.h>

#define B_   4
#define L_   4096
#define D_   1024
#define H_   16
#define DK_  64
#define BH_  (B_ * H_)
#define TOPK 8
#define M_   (B_ * L_)   // 16384

// ---------------- scratch (device globals; no runtime allocation) ----------
__device__ float g_Qp[M_ * D_];
__device__ float g_Kp[M_ * D_];
__device__ float g_Vp[M_ * D_];
__device__ float g_pre[M_ * D_];
__device__ float g_qm[BH_ * L_];
__device__ float g_km[BH_ * L_];
__device__ float g_corr[BH_ * L_];
__device__ float g_w[BH_ * TOPK];
__device__ int   g_delays[BH_ * TOPK];

// ---------------- tf32 mma GEMM -------------------------------------------
// C[M,1024] = A[M,1024] @ W[1024,1024] + bias
// block tile 128x128x32, 256 threads (8 warps, 4x2), warp tile 32x64
// 3-stage cp.async pipeline, XOR-swizzled smem (conflict-free fragment LDS)

#define A_ST_F 4096            // 128 rows x 32 k  (floats)
#define B_ST_F 4096            // 32 k x 128 n
#define STAGE_F 8192
#define STAGE_BYTES (STAGE_F * 4)
#define GEMM_SMEM (3 * STAGE_BYTES)   // 96 KB

__device__ __forceinline__ uint32_t smem_u32(const void* p) {
    uint32_t a;
    asm("{ .reg .u64 t; cvta.to.shared.u64 t, %1; cvt.u32.u64 %0, t; }"
        : "=r"(a) : "l"(p));
    return a;
}
__device__ __forceinline__ void cp16(uint32_t dst, const void* src) {
    asm volatile("cp.async.cg.shared.global [%0], [%1], 16;"
                 :: "r"(dst), "l"(src));
}
__device__ __forceinline__ uint32_t f2tf32(float f) {
    uint32_t u;
    asm("cvt.rna.tf32.f32 %0, %1;" : "=r"(u) : "f"(f));
    return u;
}
__device__ __forceinline__ void mma_tf32(float* d, const uint32_t* a, const uint32_t* b) {
    asm volatile(
        "mma.sync.aligned.m16n8k8.row.col.f32.tf32.tf32.f32 "
        "{%0,%1,%2,%3}, {%4,%5,%6,%7}, {%8,%9}, {%0,%1,%2,%3};"
        : "+f"(d[0]), "+f"(d[1]), "+f"(d[2]), "+f"(d[3])
        : "r"(a[0]), "r"(a[1]), "r"(a[2]), "r"(a[3]), "r"(b[0]), "r"(b[1]));
}

__global__ __launch_bounds__(256) void gemm_tf32_kernel(
    const float* __restrict__ A, const float* __restrict__ W,
    const float* __restrict__ bias, float* __restrict__ C)
{
    extern __shared__ float sm[];
    const uint32_t su = smem_u32(sm);
    const int tid = threadIdx.x;
    const int bn = blockIdx.x;           // 0..7
    const int bm = blockIdx.y;           // 0..127
    const int wid = tid >> 5, lane = tid & 31;
    const int wm = wid >> 1, wn = wid & 1;
    const int qr = lane >> 2, qc = lane & 3;

    // global load bases
    const float* Ab = A + (size_t)(bm * 128 + (tid >> 3)) * 1024 + (tid & 7) * 4;
    const float* Wb = W + (size_t)(tid >> 5) * 1024 + bn * 128 + (tid & 31) * 4;

    // smem byte offsets (per pass), swizzled
    uint32_t saoff[4], sboff[4];
    #pragma unroll
    for (int p = 0; p < 4; p++) {
        int row = (tid >> 3) + p * 32;
        saoff[p] = (row * 32 + (((tid & 7) ^ (row & 7)) << 2)) * 4;
        int k = (tid >> 5) + p * 8;
        sboff[p] = (A_ST_F + k * 128 + (((tid & 31) << 2) ^ ((k & 3) << 3))) * 4;
    }

    float acc[2][8][4];
    #pragma unroll
    for (int mb = 0; mb < 2; mb++)
        #pragma unroll
        for (int j = 0; j < 8; j++)
            #pragma unroll
            for (int v = 0; v < 4; v++) acc[mb][j][v] = 0.0f;

    // ---- load stage helper (macro-ish via lambda) ----
    auto load_stage = [&](int st, int kt) {
        uint32_t base = su + st * STAGE_BYTES;
        #pragma unroll
        for (int p = 0; p < 4; p++) {
            cp16(base + saoff[p], Ab + kt * 32 + p * 32 * 1024);
            cp16(base + sboff[p], Wb + (size_t)(kt * 32 + p * 8) * 1024);
        }
    };

    load_stage(0, 0);
    asm volatile("cp.async.commit_group;");
    load_stage(1, 1);
    asm volatile("cp.async.commit_group;");

    const int rowa0 = wm * 32 + qr;
    const int nbase = wn * 64 + qr;

    for (int kt = 0; kt < 32; kt++) {
        const int st = kt % 3;
        if (kt < 30) asm volatile("cp.async.wait_group 1;");
        else         asm volatile("cp.async.wait_group 0;");
        __syncthreads();
        if (kt < 30) {
            load_stage((kt + 2) % 3, kt + 2);
            asm volatile("cp.async.commit_group;");
        }

        const float* As = sm + st * STAGE_F;
        const float* Bs = As + A_ST_F;

        #pragma unroll
        for (int s = 0; s < 4; s++) {
            uint32_t afr[2][4];
            #pragma unroll
            for (int mb = 0; mb < 2; mb++) {
                int row = rowa0 + mb * 16;          // row&7 == qr
                int s0 = (((s * 2)     ^ qr) << 2) + qc;
                int s1 = (((s * 2 + 1) ^ qr) << 2) + qc;
                afr[mb][0] = f2tf32(As[row * 32 + s0]);
                afr[mb][1] = f2tf32(As[(row + 8) * 32 + s0]);
                afr[mb][2] = f2tf32(As[row * 32 + s1]);
                afr[mb][3] = f2tf32(As[(row + 8) * 32 + s1]);
            }
            uint32_t bfr[8][2];
            #pragma unroll
            for (int j = 0; j < 8; j++) {
                int nx = (nbase + j * 8) ^ (qc << 3);
                bfr[j][0] = f2tf32(Bs[(s * 8 + qc) * 128 + nx]);
                bfr[j][1] = f2tf32(Bs[(s * 8 + qc + 4) * 128 + nx]);
            }
            #pragma unroll
            for (int mb = 0; mb < 2; mb++)
                #pragma unroll
                for (int j = 0; j < 8; j++)
                    mma_tf32(acc[mb][j], afr[mb], bfr[j]);
        }
    }

    // epilogue
    #pragma unroll
    for (int mb = 0; mb < 2; mb++) {
        int row = bm * 128 + wm * 32 + mb * 16 + qr;
        #pragma unroll
        for (int j = 0; j < 8; j++) {
            int col = bn * 128 + wn * 64 + j * 8 + qc * 2;
            float2 bb = *(const float2*)(bias + col);
            float2 o0 = make_float2(acc[mb][j][0] + bb.x, acc[mb][j][1] + bb.y);
            float2 o1 = make_float2(acc[mb][j][2] + bb.x, acc[mb][j][3] + bb.y);
            *(float2*)(C + (size_t)row * 1024 + col)       = o0;
            *(float2*)(C + (size_t)(row + 8) * 1024 + col) = o1;
        }
    }
}

// ---------------- per-head means -------------------------------------------
__global__ __launch_bounds__(256) void means_kernel(
    const float* __restrict__ Qp, const float* __restrict__ Kp,
    float* __restrict__ qm, float* __restrict__ km)
{
    int warp = (blockIdx.x * blockDim.x + threadIdx.x) >> 5;
    int lane = threadIdx.x & 31;
    if (warp >= BH_ * L_) return;
    int bh = warp >> 12;
    int l  = warp & (L_ - 1);
    int b  = bh >> 4;
    int h  = bh & (H_ - 1);
    const float* qp = Qp + (size_t)(b * L_ + l) * D_ + h * DK_ + lane * 2;
    const float* kp = Kp + (size_t)(b * L_ + l) * D_ + h * DK_ + lane * 2;
    float2 q2 = *(const float2*)qp;
    float2 k2 = *(const float2*)kp;
    float qs = q2.x + q2.y;
    float ks = k2.x + k2.y;
    #pragma unroll
    for (int o = 16; o > 0; o >>= 1) {
        qs += __shfl_xor_sync(0xFFFFFFFFu, qs, o);
        ks += __shfl_xor_sync(0xFFFFFFFFu, ks, o);
    }
    if (lane == 0) {
        qm[warp] = qs * (1.0f / DK_);
        km[warp] = ks * (1.0f / DK_);
    }
}

// ---------------- circular cross-correlation -------------------------------
__global__ __launch_bounds__(256) void corr_kernel(
    const float* __restrict__ qm, const float* __restrict__ km,
    float* __restrict__ corr)
{
    __shared__ float sq[L_];
    __shared__ float sk[6144];

    const int bh = blockIdx.x;
    const int chunk = blockIdx.y;
    const int wb = (1 - chunk) * 2048;

    const float* q = qm + bh * L_;
    const float* k = km + bh * L_;
    for (int i = threadIdx.x; i < L_; i += 256) sq[i] = q[i];
    for (int i = threadIdx.x; i < 6144; i += 256) sk[i] = k[(i + wb) & (L_ - 1)];
    __syncthreads();

    const int t = threadIdx.x;
    float acc[8];
    #pragma unroll
    for (int j = 0; j < 8; j++) acc[j] = 0.0f;
    const float* kp = sk + 2048 - t;
    #pragma unroll 4
    for (int m = 0; m < L_; m++) {
        float qv = sq[m];
        #pragma unroll
        for (int j = 0; j < 8; j++)
            acc[j] += qv * kp[m - 256 * j];
    }
    #pragma unroll
    for (int j = 0; j < 8; j++)
        corr[bh * L_ + chunk * 2048 + t + 256 * j] = acc[j];
}

// ---------------- top-8 + softmax ------------------------------------------
__global__ __launch_bounds__(256) void top8_kernel(
    const float* __restrict__ corr, float* __restrict__ w, int* __restrict__ delays)
{
    __shared__ float sc[L_];
    __shared__ float svals[256];
    __shared__ int   sidx[256];
    __shared__ float topv[TOPK];
    __shared__ int   topi[TOPK];

    const int bh = blockIdx.x;
    for (int i = threadIdx.x; i < L_; i += 256) sc[i] = corr[bh * L_ + i];
    __syncthreads();

    for (int r = 0; r < TOPK; r++) {
        float best = -INFINITY; int bi = 0;
        for (int i = threadIdx.x; i < L_; i += 256) {
            float v = sc[i];
            if (v > best) { best = v; bi = i; }
        }
        svals[threadIdx.x] = best;
        sidx[threadIdx.x] = bi;
        __syncthreads();
        for (int s = 128; s > 0; s >>= 1) {
            if (threadIdx.x < s) {
                float v2 = svals[threadIdx.x + s];
                int   i2 = sidx[threadIdx.x + s];
                float v1 = svals[threadIdx.x];
                int   i1 = sidx[threadIdx.x];
                if (v2 > v1 || (v2 == v1 && i2 < i1)) {
                    svals[threadIdx.x] = v2;
                    sidx[threadIdx.x] = i2;
                }
            }
            __syncthreads();
        }
        if (threadIdx.x == 0) {
            topv[r] = svals[0];
            topi[r] = sidx[0];
            sc[sidx[0]] = -INFINITY;
        }
        __syncthreads();
    }

    if (threadIdx.x == 0) {
        float mx = topv[0];
        float e[TOPK], s = 0.0f;
        #pragma unroll
        for (int r = 0; r < TOPK; r++) { e[r] = expf(topv[r] - mx); s += e[r]; }
        float inv = 1.0f / s;
        #pragma unroll
        for (int r = 0; r < TOPK; r++) {
            w[bh * TOPK + r] = e[r] * inv;
            delays[bh * TOPK + r] = topi[r];
        }
    }
}

// ---------------- weighted circular-roll aggregation ----------------------
__global__ __launch_bounds__(256) void gather_kernel(
    const float* __restrict__ Vp, const float* __restrict__ w,
    const int* __restrict__ delays, float* __restrict__ out)
{
    unsigned gid = blockIdx.x * blockDim.x + threadIdx.x;  // one float4 each
    int d4 = gid & 255;
    int l  = (gid >> 8) & (L_ - 1);
    int b  = gid >> 20;
    int h  = d4 >> 4;
    int bh = b * H_ + h;

    float4 a = make_float4(0.f, 0.f, 0.f, 0.f);
    #pragma unroll
    for (int r = 0; r < TOPK; r++) {
        float wr = __ldg(&w[bh * TOPK + r]);
        int   dl = __ldg(&delays[bh * TOPK + r]);
        int   lm = (l - dl) & (L_ - 1);
        const float4 v = *(const float4*)(Vp + (size_t)(b * L_ + lm) * D_ + d4 * 4);
        a.x += wr * v.x; a.y += wr * v.y; a.z += wr * v.z; a.w += wr * v.w;
    }
    *(float4*)(out + (size_t)gid * 4) = a;
}

// ---------------- launch ---------------------------------------------------
extern "C" void kernel_launch(void* const* d_in, const int* in_sizes, int n_in,
                              void* d_out, int out_size)
{
    const float* queries = (const float*)d_in[0];
    const float* keys    = (const float*)d_in[1];
    const float* values  = (const float*)d_in[2];
    const float* Wq = (const float*)d_in[3];
    const float* bq = (const float*)d_in[4];
    const float* Wk = (const float*)d_in[5];
    const float* bk = (const float*)d_in[6];
    const float* Wv = (const float*)d_in[7];
    const float* bv = (const float*)d_in[8];
    const float* Wo = (const float*)d_in[9];
    const float* bo = (const float*)d_in[10];
    float* out = (float*)d_out;

    float *Qp, *Kp, *Vp, *pre, *qm, *km, *corr, *w;
    int* delays;
    cudaGetSymbolAddress((void**)&Qp, g_Qp);
    cudaGetSymbolAddress((void**)&Kp, g_Kp);
    cudaGetSymbolAddress((void**)&Vp, g_Vp);
    cudaGetSymbolAddress((void**)&pre, g_pre);
    cudaGetSymbolAddress((void**)&qm, g_qm);
    cudaGetSymbolAddress((void**)&km, g_km);
    cudaGetSymbolAddress((void**)&corr, g_corr);
    cudaGetSymbolAddress((void**)&w, g_w);
    cudaGetSymbolAddress((void**)&delays, g_delays);

    cudaFuncSetAttribute(gemm_tf32_kernel,
                         cudaFuncAttributeMaxDynamicSharedMemorySize, GEMM_SMEM);

    dim3 gemm_grid(8, 128);

    gemm_tf32_kernel<<<gemm_grid, 256, GEMM_SMEM>>>(queries, Wq, bq, Qp);
    gemm_tf32_kernel<<<gemm_grid, 256, GEMM_SMEM>>>(keys,    Wk, bk, Kp);
    gemm_tf32_kernel<<<gemm_grid, 256, GEMM_SMEM>>>(values,  Wv, bv, Vp);

    means_kernel<<<(BH_ * L_ * 32) / 256, 256>>>(Qp, Kp, qm, km);

    dim3 corr_grid(BH_, 2);
    corr_kernel<<<corr_grid, 256>>>(qm, km, corr);

    top8_kernel<<<BH_, 256>>>(corr, w, delays);

    gather_kernel<<<(M_ * D_ / 4) / 256, 256>>>(Vp, w, delays, pre);

    gemm_tf32_kernel<<<gemm_grid, 256, GEMM_SMEM>>>(pre, Wo, bo, out);
}

// round 6
// speedup vs baseline: 1.0105x; 1.0105x over previous
#include <cuda_runtime.h>
#include <cuda_bf16.h>
#include <math.h>
#include <stdint.h>

#define B_   4
#define L_   4096
#define D_   1024
#define H_   16
#define DK_  64
#define BH_  (B_ * H_)
#define TOPK 8
#define M_   (B_ * L_)   // 16384

// ---------------- scratch (device globals; no runtime allocation) ----------
__device__ float g_Qp[M_ * D_];
__device__ float g_Kp[M_ * D_];
__device__ float g_Vp[M_ * D_];
__device__ float g_pre[M_ * D_];
__device__ float g_qm[BH_ * L_];
__device__ float g_km[BH_ * L_];
__device__ float g_corr[BH_ * L_];
__device__ float g_w[BH_ * TOPK];
__device__ int   g_delays[BH_ * TOPK];

// ---------------- tf32 mma GEMM -------------------------------------------
// C[M,1024] = A[M,1024] @ W[1024,1024] + bias
// block tile 128x128x32, 256 threads (8 warps, 4x2), warp tile 32x64
// 3-stage cp.async pipeline, XOR-swizzled smem (conflict-free fragment LDS)

#define A_ST_F 4096            // 128 rows x 32 k  (floats)
#define B_ST_F 4096            // 32 k x 128 n
#define STAGE_F 8192
#define STAGE_BYTES (STAGE_F * 4)
#define GEMM_SMEM (3 * STAGE_BYTES)   // 96 KB

__device__ __forceinline__ uint32_t smem_u32(const void* p) {
    uint32_t a;
    asm("{ .reg .u64 t; cvta.to.shared.u64 t, %1; cvt.u32.u64 %0, t; }"
        : "=r"(a) : "l"(p));
    return a;
}
__device__ __forceinline__ void cp16(uint32_t dst, const void* src) {
    asm volatile("cp.async.cg.shared.global [%0], [%1], 16;"
                 :: "r"(dst), "l"(src));
}
__device__ __forceinline__ uint32_t f2tf32(float f) {
    uint32_t u;
    asm("cvt.rna.tf32.f32 %0, %1;" : "=r"(u) : "f"(f));
    return u;
}
__device__ __forceinline__ void mma_tf32(float* d, const uint32_t* a, const uint32_t* b) {
    asm volatile(
        "mma.sync.aligned.m16n8k8.row.col.f32.tf32.tf32.f32 "
        "{%0,%1,%2,%3}, {%4,%5,%6,%7}, {%8,%9}, {%0,%1,%2,%3};"
        : "+f"(d[0]), "+f"(d[1]), "+f"(d[2]), "+f"(d[3])
        : "r"(a[0]), "r"(a[1]), "r"(a[2]), "r"(a[3]), "r"(b[0]), "r"(b[1]));
}

__global__ __launch_bounds__(256) void gemm_tf32_kernel(
    const float* __restrict__ A, const float* __restrict__ W,
    const float* __restrict__ bias, float* __restrict__ C)
{
    extern __shared__ float sm[];
    const uint32_t su = smem_u32(sm);
    const int tid = threadIdx.x;
    const int bn = blockIdx.x;           // 0..7
    const int bm = blockIdx.y;           // 0..127
    const int wid = tid >> 5, lane = tid & 31;
    const int wm = wid >> 1, wn = wid & 1;
    const int qr = lane >> 2, qc = lane & 3;

    // global load bases
    const float* Ab = A + (size_t)(bm * 128 + (tid >> 3)) * 1024 + (tid & 7) * 4;
    const float* Wb = W + (size_t)(tid >> 5) * 1024 + bn * 128 + (tid & 31) * 4;

    // smem byte offsets (per pass), swizzled
    uint32_t saoff[4], sboff[4];
    #pragma unroll
    for (int p = 0; p < 4; p++) {
        int row = (tid >> 3) + p * 32;
        saoff[p] = (row * 32 + (((tid & 7) ^ (row & 7)) << 2)) * 4;
        int k = (tid >> 5) + p * 8;
        sboff[p] = (A_ST_F + k * 128 + (((tid & 31) << 2) ^ ((k & 3) << 3))) * 4;
    }

    float acc[2][8][4];
    #pragma unroll
    for (int mb = 0; mb < 2; mb++)
        #pragma unroll
        for (int j = 0; j < 8; j++)
            #pragma unroll
            for (int v = 0; v < 4; v++) acc[mb][j][v] = 0.0f;

    // ---- load stage helper (macro-ish via lambda) ----
    auto load_stage = [&](int st, int kt) {
        uint32_t base = su + st * STAGE_BYTES;
        #pragma unroll
        for (int p = 0; p < 4; p++) {
            cp16(base + saoff[p], Ab + kt * 32 + p * 32 * 1024);
            cp16(base + sboff[p], Wb + (size_t)(kt * 32 + p * 8) * 1024);
        }
    };

    load_stage(0, 0);
    asm volatile("cp.async.commit_group;");
    load_stage(1, 1);
    asm volatile("cp.async.commit_group;");

    const int rowa0 = wm * 32 + qr;
    const int nbase = wn * 64 + qr;

    for (int kt = 0; kt < 32; kt++) {
        const int st = kt % 3;
        if (kt < 30) asm volatile("cp.async.wait_group 1;");
        else         asm volatile("cp.async.wait_group 0;");
        __syncthreads();
        if (kt < 30) {
            load_stage((kt + 2) % 3, kt + 2);
            asm volatile("cp.async.commit_group;");
        }

        const float* As = sm + st * STAGE_F;
        const float* Bs = As + A_ST_F;

        #pragma unroll
        for (int s = 0; s < 4; s++) {
            uint32_t afr[2][4];
            #pragma unroll
            for (int mb = 0; mb < 2; mb++) {
                int row = rowa0 + mb * 16;          // row&7 == qr
                int s0 = (((s * 2)     ^ qr) << 2) + qc;
                int s1 = (((s * 2 + 1) ^ qr) << 2) + qc;
                afr[mb][0] = f2tf32(As[row * 32 + s0]);
                afr[mb][1] = f2tf32(As[(row + 8) * 32 + s0]);
                afr[mb][2] = f2tf32(As[row * 32 + s1]);
                afr[mb][3] = f2tf32(As[(row + 8) * 32 + s1]);
            }
            uint32_t bfr[8][2];
            #pragma unroll
            for (int j = 0; j < 8; j++) {
                int nx = (nbase + j * 8) ^ (qc << 3);
                bfr[j][0] = f2tf32(Bs[(s * 8 + qc) * 128 + nx]);
                bfr[j][1] = f2tf32(Bs[(s * 8 + qc + 4) * 128 + nx]);
            }
            #pragma unroll
            for (int mb = 0; mb < 2; mb++)
                #pragma unroll
                for (int j = 0; j < 8; j++)
                    mma_tf32(acc[mb][j], afr[mb], bfr[j]);
        }
    }

    // epilogue
    #pragma unroll
    for (int mb = 0; mb < 2; mb++) {
        int row = bm * 128 + wm * 32 + mb * 16 + qr;
        #pragma unroll
        for (int j = 0; j < 8; j++) {
            int col = bn * 128 + wn * 64 + j * 8 + qc * 2;
            float2 bb = *(const float2*)(bias + col);
            float2 o0 = make_float2(acc[mb][j][0] + bb.x, acc[mb][j][1] + bb.y);
            float2 o1 = make_float2(acc[mb][j][2] + bb.x, acc[mb][j][3] + bb.y);
            *(float2*)(C + (size_t)row * 1024 + col)       = o0;
            *(float2*)(C + (size_t)(row + 8) * 1024 + col) = o1;
        }
    }
}

// ---------------- per-head means -------------------------------------------
__global__ __launch_bounds__(256) void means_kernel(
    const float* __restrict__ Qp, const float* __restrict__ Kp,
    float* __restrict__ qm, float* __restrict__ km)
{
    int warp = (blockIdx.x * blockDim.x + threadIdx.x) >> 5;
    int lane = threadIdx.x & 31;
    if (warp >= BH_ * L_) return;
    int bh = warp >> 12;
    int l  = warp & (L_ - 1);
    int b  = bh >> 4;
    int h  = bh & (H_ - 1);
    const float* qp = Qp + (size_t)(b * L_ + l) * D_ + h * DK_ + lane * 2;
    const float* kp = Kp + (size_t)(b * L_ + l) * D_ + h * DK_ + lane * 2;
    float2 q2 = *(const float2*)qp;
    float2 k2 = *(const float2*)kp;
    float qs = q2.x + q2.y;
    float ks = k2.x + k2.y;
    #pragma unroll
    for (int o = 16; o > 0; o >>= 1) {
        qs += __shfl_xor_sync(0xFFFFFFFFu, qs, o);
        ks += __shfl_xor_sync(0xFFFFFFFFu, ks, o);
    }
    if (lane == 0) {
        qm[warp] = qs * (1.0f / DK_);
        km[warp] = ks * (1.0f / DK_);
    }
}

// ---------------- circular cross-correlation -------------------------------
__global__ __launch_bounds__(256) void corr_kernel(
    const float* __restrict__ qm, const float* __restrict__ km,
    float* __restrict__ corr)
{
    __shared__ float sq[L_];
    __shared__ float sk[6144];

    const int bh = blockIdx.x;
    const int chunk = blockIdx.y;
    const int wb = (1 - chunk) * 2048;

    const float* q = qm + bh * L_;
    const float* k = km + bh * L_;
    for (int i = threadIdx.x; i < L_; i += 256) sq[i] = q[i];
    for (int i = threadIdx.x; i < 6144; i += 256) sk[i] = k[(i + wb) & (L_ - 1)];
    __syncthreads();

    const int t = threadIdx.x;
    float acc[8];
    #pragma unroll
    for (int j = 0; j < 8; j++) acc[j] = 0.0f;
    const float* kp = sk + 2048 - t;
    #pragma unroll 4
    for (int m = 0; m < L_; m++) {
        float qv = sq[m];
        #pragma unroll
        for (int j = 0; j < 8; j++)
            acc[j] += qv * kp[m - 256 * j];
    }
    #pragma unroll
    for (int j = 0; j < 8; j++)
        corr[bh * L_ + chunk * 2048 + t + 256 * j] = acc[j];
}

// ---------------- top-8 + softmax ------------------------------------------
__global__ __launch_bounds__(256) void top8_kernel(
    const float* __restrict__ corr, float* __restrict__ w, int* __restrict__ delays)
{
    __shared__ float sc[L_];
    __shared__ float svals[256];
    __shared__ int   sidx[256];
    __shared__ float topv[TOPK];
    __shared__ int   topi[TOPK];

    const int bh = blockIdx.x;
    for (int i = threadIdx.x; i < L_; i += 256) sc[i] = corr[bh * L_ + i];
    __syncthreads();

    for (int r = 0; r < TOPK; r++) {
        float best = -INFINITY; int bi = 0;
        for (int i = threadIdx.x; i < L_; i += 256) {
            float v = sc[i];
            if (v > best) { best = v; bi = i; }
        }
        svals[threadIdx.x] = best;
        sidx[threadIdx.x] = bi;
        __syncthreads();
        for (int s = 128; s > 0; s >>= 1) {
            if (threadIdx.x < s) {
                float v2 = svals[threadIdx.x + s];
                int   i2 = sidx[threadIdx.x + s];
                float v1 = svals[threadIdx.x];
                int   i1 = sidx[threadIdx.x];
                if (v2 > v1 || (v2 == v1 && i2 < i1)) {
                    svals[threadIdx.x] = v2;
                    sidx[threadIdx.x] = i2;
                }
            }
            __syncthreads();
        }
        if (threadIdx.x == 0) {
            topv[r] = svals[0];
            topi[r] = sidx[0];
            sc[sidx[0]] = -INFINITY;
        }
        __syncthreads();
    }

    if (threadIdx.x == 0) {
        float mx = topv[0];
        float e[TOPK], s = 0.0f;
        #pragma unroll
        for (int r = 0; r < TOPK; r++) { e[r] = expf(topv[r] - mx); s += e[r]; }
        float inv = 1.0f / s;
        #pragma unroll
        for (int r = 0; r < TOPK; r++) {
            w[bh * TOPK + r] = e[r] * inv;
            delays[bh * TOPK + r] = topi[r];
        }
    }
}

// ---------------- weighted circular-roll aggregation ----------------------
__global__ __launch_bounds__(256) void gather_kernel(
    const float* __restrict__ Vp, const float* __restrict__ w,
    const int* __restrict__ delays, float* __restrict__ out)
{
    unsigned gid = blockIdx.x * blockDim.x + threadIdx.x;  // one float4 each
    int d4 = gid & 255;
    int l  = (gid >> 8) & (L_ - 1);
    int b  = gid >> 20;
    int h  = d4 >> 4;
    int bh = b * H_ + h;

    float4 a = make_float4(0.f, 0.f, 0.f, 0.f);
    #pragma unroll
    for (int r = 0; r < TOPK; r++) {
        float wr = __ldg(&w[bh * TOPK + r]);
        int   dl = __ldg(&delays[bh * TOPK + r]);
        int   lm = (l - dl) & (L_ - 1);
        const float4 v = *(const float4*)(Vp + (size_t)(b * L_ + lm) * D_ + d4 * 4);
        a.x += wr * v.x; a.y += wr * v.y; a.z += wr * v.z; a.w += wr * v.w;
    }
    *(float4*)(out + (size_t)gid * 4) = a;
}

// ---------------- launch ---------------------------------------------------
extern "C" void kernel_launch(void* const* d_in, const int* in_sizes, int n_in,
                              void* d_out, int out_size)
{
    const float* queries = (const float*)d_in[0];
    const float* keys    = (const float*)d_in[1];
    const float* values  = (const float*)d_in[2];
    const float* Wq = (const float*)d_in[3];
    const float* bq = (const float*)d_in[4];
    const float* Wk = (const float*)d_in[5];
    const float* bk = (const float*)d_in[6];
    const float* Wv = (const float*)d_in[7];
    const float* bv = (const float*)d_in[8];
    const float* Wo = (const float*)d_in[9];
    const float* bo = (const float*)d_in[10];
    float* out = (float*)d_out;

    float *Qp, *Kp, *Vp, *pre, *qm, *km, *corr, *w;
    int* delays;
    cudaGetSymbolAddress((void**)&Qp, g_Qp);
    cudaGetSymbolAddress((void**)&Kp, g_Kp);
    cudaGetSymbolAddress((void**)&Vp, g_Vp);
    cudaGetSymbolAddress((void**)&pre, g_pre);
    cudaGetSymbolAddress((void**)&qm, g_qm);
    cudaGetSymbolAddress((void**)&km, g_km);
    cudaGetSymbolAddress((void**)&corr, g_corr);
    cudaGetSymbolAddress((void**)&w, g_w);
    cudaGetSymbolAddress((void**)&delays, g_delays);

    cudaFuncSetAttribute(gemm_tf32_kernel,
                         cudaFuncAttributeMaxDynamicSharedMemorySize, GEMM_SMEM);

    dim3 gemm_grid(8, 128);

    gemm_tf32_kernel<<<gemm_grid, 256, GEMM_SMEM>>>(queries, Wq, bq, Qp);
    gemm_tf32_kernel<<<gemm_grid, 256, GEMM_SMEM>>>(keys,    Wk, bk, Kp);
    gemm_tf32_kernel<<<gemm_grid, 256, GEMM_SMEM>>>(values,  Wv, bv, Vp);

    means_kernel<<<(BH_ * L_ * 32) / 256, 256>>>(Qp, Kp, qm, km);

    dim3 corr_grid(BH_, 2);
    corr_kernel<<<corr_grid, 256>>>(qm, km, corr);

    top8_kernel<<<BH_, 256>>>(corr, w, delays);

    gather_kernel<<<(M_ * D_ / 4) / 256, 256>>>(Vp, w, delays, pre);

    gemm_tf32_kernel<<<gemm_grid, 256, GEMM_SMEM>>>(pre, Wo, bo, out);
}

// round 7
// speedup vs baseline: 1.7774x; 1.7589x over previous
#include <cuda_runtime.h>
#include <cuda_bf16.h>
#include <math.h>
#include <stdint.h>

#define B_   4
#define L_   4096
#define D_   1024
#define H_   16
#define DK_  64
#define BH_  (B_ * H_)
#define TOPK 8
#define M_   (B_ * L_)   // 16384

// ---------------- scratch (device globals; no runtime allocation) ----------
__device__ float g_Vp[M_ * D_];
__device__ float g_pre[M_ * D_];
__device__ float g_qm[BH_ * L_];
__device__ float g_km[BH_ * L_];
__device__ float g_Wm[2 * H_ * D_];     // [t][h][d] mean-reduced weights
__device__ float g_w[BH_ * TOPK];
__device__ int   g_delays[BH_ * TOPK];

// ---------------- tf32 mma GEMM (proven R6 kernel) --------------------------
#define A_ST_F 4096
#define B_ST_F 4096
#define STAGE_F 8192
#define STAGE_BYTES (STAGE_F * 4)
#define GEMM_SMEM (3 * STAGE_BYTES)   // 96 KB

__device__ __forceinline__ uint32_t smem_u32(const void* p) {
    uint32_t a;
    asm("{ .reg .u64 t; cvta.to.shared.u64 t, %1; cvt.u32.u64 %0, t; }"
        : "=r"(a) : "l"(p));
    return a;
}
__device__ __forceinline__ void cp16(uint32_t dst, const void* src) {
    asm volatile("cp.async.cg.shared.global [%0], [%1], 16;"
                 :: "r"(dst), "l"(src));
}
__device__ __forceinline__ uint32_t f2tf32(float f) {
    uint32_t u;
    asm("cvt.rna.tf32.f32 %0, %1;" : "=r"(u) : "f"(f));
    return u;
}
__device__ __forceinline__ void mma_tf32(float* d, const uint32_t* a, const uint32_t* b) {
    asm volatile(
        "mma.sync.aligned.m16n8k8.row.col.f32.tf32.tf32.f32 "
        "{%0,%1,%2,%3}, {%4,%5,%6,%7}, {%8,%9}, {%0,%1,%2,%3};"
        : "+f"(d[0]), "+f"(d[1]), "+f"(d[2]), "+f"(d[3])
        : "r"(a[0]), "r"(a[1]), "r"(a[2]), "r"(a[3]), "r"(b[0]), "r"(b[1]));
}

__global__ __launch_bounds__(256) void gemm_tf32_kernel(
    const float* __restrict__ A, const float* __restrict__ W,
    const float* __restrict__ bias, float* __restrict__ C)
{
    extern __shared__ float sm[];
    const uint32_t su = smem_u32(sm);
    const int tid = threadIdx.x;
    const int bn = blockIdx.x;
    const int bm = blockIdx.y;
    const int wid = tid >> 5, lane = tid & 31;
    const int wm = wid >> 1, wn = wid & 1;
    const int qr = lane >> 2, qc = lane & 3;

    const float* Ab = A + (size_t)(bm * 128 + (tid >> 3)) * 1024 + (tid & 7) * 4;
    const float* Wb = W + (size_t)(tid >> 5) * 1024 + bn * 128 + (tid & 31) * 4;

    uint32_t saoff[4], sboff[4];
    #pragma unroll
    for (int p = 0; p < 4; p++) {
        int row = (tid >> 3) + p * 32;
        saoff[p] = (row * 32 + (((tid & 7) ^ (row & 7)) << 2)) * 4;
        int k = (tid >> 5) + p * 8;
        sboff[p] = (A_ST_F + k * 128 + (((tid & 31) << 2) ^ ((k & 3) << 3))) * 4;
    }

    float acc[2][8][4];
    #pragma unroll
    for (int mb = 0; mb < 2; mb++)
        #pragma unroll
        for (int j = 0; j < 8; j++)
            #pragma unroll
            for (int v = 0; v < 4; v++) acc[mb][j][v] = 0.0f;

    auto load_stage = [&](int st, int kt) {
        uint32_t base = su + st * STAGE_BYTES;
        #pragma unroll
        for (int p = 0; p < 4; p++) {
            cp16(base + saoff[p], Ab + kt * 32 + p * 32 * 1024);
            cp16(base + sboff[p], Wb + (size_t)(kt * 32 + p * 8) * 1024);
        }
    };

    load_stage(0, 0);
    asm volatile("cp.async.commit_group;");
    load_stage(1, 1);
    asm volatile("cp.async.commit_group;");

    const int rowa0 = wm * 32 + qr;
    const int nbase = wn * 64 + qr;

    for (int kt = 0; kt < 32; kt++) {
        const int st = kt % 3;
        if (kt < 30) asm volatile("cp.async.wait_group 1;");
        else         asm volatile("cp.async.wait_group 0;");
        __syncthreads();
        if (kt < 30) {
            load_stage((kt + 2) % 3, kt + 2);
            asm volatile("cp.async.commit_group;");
        }

        const float* As = sm + st * STAGE_F;
        const float* Bs = As + A_ST_F;

        #pragma unroll
        for (int s = 0; s < 4; s++) {
            uint32_t afr[2][4];
            #pragma unroll
            for (int mb = 0; mb < 2; mb++) {
                int row = rowa0 + mb * 16;
                int s0 = (((s * 2)     ^ qr) << 2) + qc;
                int s1 = (((s * 2 + 1) ^ qr) << 2) + qc;
                afr[mb][0] = f2tf32(As[row * 32 + s0]);
                afr[mb][1] = f2tf32(As[(row + 8) * 32 + s0]);
                afr[mb][2] = f2tf32(As[row * 32 + s1]);
                afr[mb][3] = f2tf32(As[(row + 8) * 32 + s1]);
            }
            uint32_t bfr[8][2];
            #pragma unroll
            for (int j = 0; j < 8; j++) {
                int nx = (nbase + j * 8) ^ (qc << 3);
                bfr[j][0] = f2tf32(Bs[(s * 8 + qc) * 128 + nx]);
                bfr[j][1] = f2tf32(Bs[(s * 8 + qc + 4) * 128 + nx]);
            }
            #pragma unroll
            for (int mb = 0; mb < 2; mb++)
                #pragma unroll
                for (int j = 0; j < 8; j++)
                    mma_tf32(acc[mb][j], afr[mb], bfr[j]);
        }
    }

    #pragma unroll
    for (int mb = 0; mb < 2; mb++) {
        int row = bm * 128 + wm * 32 + mb * 16 + qr;
        #pragma unroll
        for (int j = 0; j < 8; j++) {
            int col = bn * 128 + wn * 64 + j * 8 + qc * 2;
            float2 bb = *(const float2*)(bias + col);
            float2 o0 = make_float2(acc[mb][j][0] + bb.x, acc[mb][j][1] + bb.y);
            float2 o1 = make_float2(acc[mb][j][2] + bb.x, acc[mb][j][3] + bb.y);
            *(float2*)(C + (size_t)row * 1024 + col)       = o0;
            *(float2*)(C + (size_t)(row + 8) * 1024 + col) = o1;
        }
    }
}

// ---------------- mean-reduced weights: Wm[t][h][d] = mean_c W[d][h*64+c] ---
__global__ __launch_bounds__(256) void wmean_kernel(
    const float* __restrict__ Wq, const float* __restrict__ Wk,
    float* __restrict__ Wm)
{
    int id = blockIdx.x * 256 + threadIdx.x;     // 0..32767
    int t = id >> 14;
    int h = (id >> 10) & 15;
    int d = id & 1023;
    const float* W = t ? Wk : Wq;
    const float4* p = (const float4*)(W + (size_t)d * 1024 + h * 64);
    float s = 0.0f;
    #pragma unroll
    for (int c = 0; c < 16; c++) {
        float4 v = __ldg(&p[c]);
        s += (v.x + v.y) + (v.z + v.w);
    }
    Wm[id] = s * (1.0f / 64.0f);
}

// ---------------- skinny mean-projection: qm/km = x @ Wm^T ------------------
// (bias dropped: corr is exactly invariant to per-head constant offsets)
// block: 256 thr, 8 warps x 4 rows = 32 rows; Wm tables (128KB) in smem.
__global__ __launch_bounds__(256) void qkmean_kernel(
    const float* __restrict__ queries, const float* __restrict__ keys,
    const float* __restrict__ Wm, float* __restrict__ qm, float* __restrict__ km)
{
    extern __shared__ float swm[];   // 32768 floats = 128KB
    const int tid = threadIdx.x;
    for (int i = tid * 4; i < 32768; i += 1024)
        *(float4*)(swm + i) = *(const float4*)(Wm + i);
    __syncthreads();

    const int w = tid >> 5, lane = tid & 31;
    const int m0 = blockIdx.x * 32 + w * 4;

    #pragma unroll
    for (int ph = 0; ph < 2; ph++) {
        const float* src = ph ? keys : queries;
        float* dst = ph ? g_km : g_qm;
        const float* base = src + (size_t)m0 * 1024 + lane * 4;
        const float* tw_ = swm + ph * 16384 + lane * 4;

        float acc[4][16];
        #pragma unroll
        for (int r = 0; r < 4; r++)
            #pragma unroll
            for (int h = 0; h < 16; h++) acc[r][h] = 0.0f;

        #pragma unroll
        for (int c = 0; c < 8; c++) {
            float4 x0 = *(const float4*)(base + 0 * 1024 + c * 128);
            float4 x1 = *(const float4*)(base + 1 * 1024 + c * 128);
            float4 x2 = *(const float4*)(base + 2 * 1024 + c * 128);
            float4 x3 = *(const float4*)(base + 3 * 1024 + c * 128);
            #pragma unroll
            for (int h = 0; h < 16; h++) {
                float4 wv = *(const float4*)(tw_ + h * 1024 + c * 128);
                acc[0][h] += x0.x*wv.x + x0.y*wv.y + x0.z*wv.z + x0.w*wv.w;
                acc[1][h] += x1.x*wv.x + x1.y*wv.y + x1.z*wv.z + x1.w*wv.w;
                acc[2][h] += x2.x*wv.x + x2.y*wv.y + x2.z*wv.z + x2.w*wv.w;
                acc[3][h] += x3.x*wv.x + x3.y*wv.y + x3.z*wv.z + x3.w*wv.w;
            }
        }

        #pragma unroll
        for (int r = 0; r < 4; r++) {
            int m = m0 + r;
            int b = m >> 12, l = m & 4095;
            float* out = dst + (((size_t)b * 16) << 12) + l;
            #pragma unroll
            for (int h = 0; h < 16; h++) {
                float v = acc[r][h];
                v += __shfl_xor_sync(0xFFFFFFFFu, v, 16);
                v += __shfl_xor_sync(0xFFFFFFFFu, v, 8);
                v += __shfl_xor_sync(0xFFFFFFFFu, v, 4);
                v += __shfl_xor_sync(0xFFFFFFFFu, v, 2);
                v += __shfl_xor_sync(0xFFFFFFFFu, v, 1);
                if (lane == h) out[(size_t)h << 12] = v;
            }
        }
    }
}

// ---------------- FFT correlation + top-8 + softmax (fused) -----------------
// corr = Re(FFT(conj(Q*conj(K))))/N via z = qm + i*km packing.
// Stockham radix-2 DIF, 12 stages, dynamic smem: buf0|buf1|tw (80KB).
__global__ __launch_bounds__(256) void fft_corr_top8_kernel(
    const float* __restrict__ qm, const float* __restrict__ km,
    float* __restrict__ w, int* __restrict__ delays)
{
    extern __shared__ float2 fsm[];
    float2* buf0 = fsm;            // 4096
    float2* buf1 = fsm + 4096;     // 4096
    float2* tw   = fsm + 8192;     // 2048
    float*  sc   = (float*)(fsm + 8192);   // alias tw (dead after FFT #2)
    __shared__ float svals[256];
    __shared__ int   sidx[256];
    __shared__ float topv[TOPK];
    __shared__ int   topi[TOPK];

    const int bh = blockIdx.x, tid = threadIdx.x;
    const float* q = qm + (size_t)bh * L_;
    const float* k = km + (size_t)bh * L_;
    for (int i = tid; i < 4096; i += 256) buf0[i] = make_float2(q[i], k[i]);
    for (int r = tid; r < 2048; r += 256) {
        float sv, cv;
        __sincosf(-6.2831853071795865f * (float)r / 4096.0f, &sv, &cv);
        tw[r] = make_float2(cv, sv);
    }
    __syncthreads();

    // FFT #1: buf0 -> buf0 (12 stages, even count)
    {
        float2 *x = buf0, *y = buf1;
        for (int t = 0; t < 12; t++) {
            int s = 1 << t;
            #pragma unroll
            for (int ii = 0; ii < 8; ii++) {
                int idx = tid + ii * 256;
                float2 a = x[idx];
                float2 b = x[idx + 2048];
                int r = idx & ~(s - 1);
                int kl = idx & (s - 1);
                float2 wv = tw[r];
                float dx = a.x - b.x, dy = a.y - b.y;
                y[2 * r + kl]     = make_float2(a.x + b.x, a.y + b.y);
                y[2 * r + kl + s] = make_float2(dx * wv.x - dy * wv.y,
                                                dx * wv.y + dy * wv.x);
            }
            __syncthreads();
            float2* t2 = x; x = y; y = t2;
        }
    }

    // Hermitian split + P = Q*conj(K); store conj(P) into buf1
    for (int i = tid; i < 4096; i += 256) {
        float2 zi = buf0[i];
        float2 zn = buf0[(4096 - i) & 4095];
        float qx = 0.5f * (zi.x + zn.x);
        float qy = 0.5f * (zi.y - zn.y);
        float ux = zi.x - zn.x;
        float uy = zi.y + zn.y;
        float kx = 0.5f * uy;
        float ky = -0.5f * ux;
        float px = qx * kx + qy * ky;
        float py = qy * kx - qx * ky;
        buf1[i] = make_float2(px, -py);
    }
    __syncthreads();

    // FFT #2: buf1 -> buf1
    {
        float2 *x = buf1, *y = buf0;
        for (int t = 0; t < 12; t++) {
            int s = 1 << t;
            #pragma unroll
            for (int ii = 0; ii < 8; ii++) {
                int idx = tid + ii * 256;
                float2 a = x[idx];
                float2 b = x[idx + 2048];
                int r = idx & ~(s - 1);
                int kl = idx & (s - 1);
                float2 wv = tw[r];
                float dx = a.x - b.x, dy = a.y - b.y;
                y[2 * r + kl]     = make_float2(a.x + b.x, a.y + b.y);
                y[2 * r + kl + s] = make_float2(dx * wv.x - dy * wv.y,
                                                dx * wv.y + dy * wv.x);
            }
            __syncthreads();
            float2* t2 = x; x = y; y = t2;
        }
    }

    // corr values (tw region reused as sc)
    for (int i = tid; i < 4096; i += 256)
        sc[i] = buf1[i].x * (1.0f / 4096.0f);
    __syncthreads();

    // top-8 + softmax (proven reduction)
    for (int r = 0; r < TOPK; r++) {
        float best = -INFINITY; int bi = 0;
        for (int i = tid; i < 4096; i += 256) {
            float v = sc[i];
            if (v > best) { best = v; bi = i; }
        }
        svals[tid] = best;
        sidx[tid] = bi;
        __syncthreads();
        for (int s = 128; s > 0; s >>= 1) {
            if (tid < s) {
                float v2 = svals[tid + s];
                int   i2 = sidx[tid + s];
                float v1 = svals[tid];
                int   i1 = sidx[tid];
                if (v2 > v1 || (v2 == v1 && i2 < i1)) {
                    svals[tid] = v2;
                    sidx[tid] = i2;
                }
            }
            __syncthreads();
        }
        if (tid == 0) {
            topv[r] = svals[0];
            topi[r] = sidx[0];
            sc[sidx[0]] = -INFINITY;
        }
        __syncthreads();
    }

    if (tid == 0) {
        float mx = topv[0];
        float e[TOPK], s = 0.0f;
        #pragma unroll
        for (int r = 0; r < TOPK; r++) { e[r] = expf(topv[r] - mx); s += e[r]; }
        float inv = 1.0f / s;
        #pragma unroll
        for (int r = 0; r < TOPK; r++) {
            w[bh * TOPK + r] = e[r] * inv;
            delays[bh * TOPK + r] = topi[r];
        }
    }
}

// ---------------- weighted circular-roll aggregation ------------------------
__global__ __launch_bounds__(256) void gather_kernel(
    const float* __restrict__ Vp, const float* __restrict__ w,
    const int* __restrict__ delays, float* __restrict__ out)
{
    unsigned gid = blockIdx.x * blockDim.x + threadIdx.x;
    int d4 = gid & 255;
    int l  = (gid >> 8) & (L_ - 1);
    int b  = gid >> 20;
    int h  = d4 >> 4;
    int bh = b * H_ + h;

    float4 a = make_float4(0.f, 0.f, 0.f, 0.f);
    #pragma unroll
    for (int r = 0; r < TOPK; r++) {
        float wr = __ldg(&w[bh * TOPK + r]);
        int   dl = __ldg(&delays[bh * TOPK + r]);
        int   lm = (l - dl) & (L_ - 1);
        const float4 v = *(const float4*)(Vp + (size_t)(b * L_ + lm) * D_ + d4 * 4);
        a.x += wr * v.x; a.y += wr * v.y; a.z += wr * v.z; a.w += wr * v.w;
    }
    *(float4*)(out + (size_t)gid * 4) = a;
}

// ---------------- launch -----------------------------------------------------
extern "C" void kernel_launch(void* const* d_in, const int* in_sizes, int n_in,
                              void* d_out, int out_size)
{
    const float* queries = (const float*)d_in[0];
    const float* keys    = (const float*)d_in[1];
    const float* values  = (const float*)d_in[2];
    const float* Wk = (const float*)d_in[5];
    const float* Wq = (const float*)d_in[3];
    const float* Wv = (const float*)d_in[7];
    const float* bv = (const float*)d_in[8];
    const float* Wo = (const float*)d_in[9];
    const float* bo = (const float*)d_in[10];
    float* out = (float*)d_out;

    float *Vp, *pre, *qm, *km, *Wm, *w;
    int* delays;
    cudaGetSymbolAddress((void**)&Vp, g_Vp);
    cudaGetSymbolAddress((void**)&pre, g_pre);
    cudaGetSymbolAddress((void**)&qm, g_qm);
    cudaGetSymbolAddress((void**)&km, g_km);
    cudaGetSymbolAddress((void**)&Wm, g_Wm);
    cudaGetSymbolAddress((void**)&w, g_w);
    cudaGetSymbolAddress((void**)&delays, g_delays);

    cudaFuncSetAttribute(gemm_tf32_kernel,
                         cudaFuncAttributeMaxDynamicSharedMemorySize, GEMM_SMEM);
    cudaFuncSetAttribute(qkmean_kernel,
                         cudaFuncAttributeMaxDynamicSharedMemorySize, 131072);
    cudaFuncSetAttribute(fft_corr_top8_kernel,
                         cudaFuncAttributeMaxDynamicSharedMemorySize, 81920);

    dim3 gemm_grid(8, 128);

    // V projection (big GEMM) + mean-path (cheap) — independent chains
    gemm_tf32_kernel<<<gemm_grid, 256, GEMM_SMEM>>>(values, Wv, bv, Vp);

    wmean_kernel<<<128, 256>>>(Wq, Wk, Wm);
    qkmean_kernel<<<512, 256, 131072>>>(queries, keys, Wm, qm, km);
    fft_corr_top8_kernel<<<BH_, 256, 81920>>>(qm, km, w, delays);

    gather_kernel<<<(M_ * D_ / 4) / 256, 256>>>(Vp, w, delays, pre);

    gemm_tf32_kernel<<<gemm_grid, 256, GEMM_SMEM>>>(pre, Wo, bo, out);
}

// round 8
// speedup vs baseline: 1.7915x; 1.0079x over previous
#include <cuda_runtime.h>
#include <cuda_bf16.h>
#include <math.h>
#include <stdint.h>

#define B_   4
#define L_   4096
#define D_   1024
#define H_   16
#define DK_  64
#define BH_  (B_ * H_)
#define TOPK 8
#define M_   (B_ * L_)   // 16384

// ---------------- scratch (device globals; no runtime allocation) ----------
__device__ float g_Vp[M_ * D_];
__device__ float g_pre[M_ * D_];
__device__ float g_Wvr[D_ * D_];        // pre-rounded+permuted Wv
__device__ float g_Wor[D_ * D_];        // pre-rounded+permuted Wo
__device__ float g_qm[BH_ * L_];
__device__ float g_km[BH_ * L_];
__device__ float g_Wm[2 * H_ * D_];
__device__ float g_w[BH_ * TOPK];
__device__ int   g_delays[BH_ * TOPK];

// ---------------- helpers ----------------------------------------------------
__device__ __forceinline__ uint32_t smem_u32(const void* p) {
    uint32_t a;
    asm("{ .reg .u64 t; cvta.to.shared.u64 t, %1; cvt.u32.u64 %0, t; }"
        : "=r"(a) : "l"(p));
    return a;
}
__device__ __forceinline__ void cp16(uint32_t dst, const void* src) {
    asm volatile("cp.async.cg.shared.global [%0], [%1], 16;"
                 :: "r"(dst), "l"(src));
}
__device__ __forceinline__ uint32_t f2tf32(float f) {
    uint32_t u;
    asm("cvt.rna.tf32.f32 %0, %1;" : "=r"(u) : "f"(f));
    return u;
}
__device__ __forceinline__ void mma_tf32(float* d, const uint32_t* a, const uint32_t* b) {
    asm volatile(
        "mma.sync.aligned.m16n8k8.row.col.f32.tf32.tf32.f32 "
        "{%0,%1,%2,%3}, {%4,%5,%6,%7}, {%8,%9}, {%0,%1,%2,%3};"
        : "+f"(d[0]), "+f"(d[1]), "+f"(d[2]), "+f"(d[3])
        : "r"(a[0]), "r"(a[1]), "r"(a[2]), "r"(a[3]), "r"(b[0]), "r"(b[1]));
}

// ---------------- W prep: tf32-round + intra-64 column permutation ----------
// Wr[k][g*64 + p] = round_tf32(W[k][g*64 + (p&7)*8 + (p>>3)])  (involution)
__global__ __launch_bounds__(256) void wprep_kernel(
    const float* __restrict__ W, float* __restrict__ Wr)
{
    int id = blockIdx.x * 256 + threadIdx.x;    // 0 .. 1024*1024-1
    int k = id >> 10;
    int c = id & 1023;
    int g = c & ~63;
    int p = c & 63;
    int v = ((p & 7) << 3) + (p >> 3);
    float x = __ldg(&W[(size_t)k * 1024 + g + v]);
    Wr[id] = __uint_as_float(f2tf32(x));
}

// ---------------- tf32 mma GEMM ----------------------------------------------
#define A_ST_F 4096
#define STAGE_F 8192
#define STAGE_BYTES (STAGE_F * 4)
#define GEMM_SMEM (3 * STAGE_BYTES)   // 96 KB

template<bool CVT_A>
__global__ __launch_bounds__(256, 2) void gemm_tf32_kernel(
    const float* __restrict__ A, const float* __restrict__ W,
    const float* __restrict__ bias, float* __restrict__ C)
{
    extern __shared__ float sm[];
    const uint32_t su = smem_u32(sm);
    const int tid = threadIdx.x;
    const int bn = blockIdx.x;
    const int bm = blockIdx.y;
    const int wid = tid >> 5, lane = tid & 31;
    const int wm = wid >> 1, wn = wid & 1;
    const int qr = lane >> 2, qc = lane & 3;

    const float* Ab = A + (size_t)(bm * 128 + (tid >> 3)) * 1024 + (tid & 7) * 4;
    const float* Wb = W + (size_t)(tid >> 5) * 1024 + bn * 128 + (tid & 31) * 4;

    uint32_t saoff[4], sboff[4];
    #pragma unroll
    for (int p = 0; p < 4; p++) {
        int row = (tid >> 3) + p * 32;
        saoff[p] = (row * 32 + (((tid & 7) ^ (row & 7)) << 2)) * 4;
        int k = (tid >> 5) + p * 8;
        sboff[p] = (A_ST_F + k * 128 + (((tid & 31) << 2) ^ ((k & 3) << 3))) * 4;
    }

    float acc[2][8][4];
    #pragma unroll
    for (int mb = 0; mb < 2; mb++)
        #pragma unroll
        for (int j = 0; j < 8; j++)
            #pragma unroll
            for (int v = 0; v < 4; v++) acc[mb][j][v] = 0.0f;

    auto load_stage = [&](int st, int kt) {
        uint32_t base = su + st * STAGE_BYTES;
        #pragma unroll
        for (int p = 0; p < 4; p++) {
            cp16(base + saoff[p], Ab + kt * 32 + p * 32 * 1024);
            cp16(base + sboff[p], Wb + (size_t)(kt * 32 + p * 8) * 1024);
        }
    };

    load_stage(0, 0);
    asm volatile("cp.async.commit_group;");
    load_stage(1, 1);
    asm volatile("cp.async.commit_group;");

    const int rowa0 = wm * 32 + qr;
    const int colb = (wn * 64 + qr * 8) ^ (qc << 3);   // permuted-W fragment base

    for (int kt = 0; kt < 32; kt++) {
        const int st = kt % 3;
        if (kt < 30) asm volatile("cp.async.wait_group 1;");
        else         asm volatile("cp.async.wait_group 0;");
        __syncthreads();
        if (kt < 30) {
            load_stage((kt + 2) % 3, kt + 2);
            asm volatile("cp.async.commit_group;");
        }

        const float* As = sm + st * STAGE_F;
        const float* Bs = As + A_ST_F;

        #pragma unroll
        for (int s = 0; s < 4; s++) {
            uint32_t afr[2][4];
            #pragma unroll
            for (int mb = 0; mb < 2; mb++) {
                int row = rowa0 + mb * 16;
                int s0 = (((s * 2)     ^ qr) << 2) + qc;
                int s1 = (((s * 2 + 1) ^ qr) << 2) + qc;
                if (CVT_A) {
                    afr[mb][0] = f2tf32(As[row * 32 + s0]);
                    afr[mb][1] = f2tf32(As[(row + 8) * 32 + s0]);
                    afr[mb][2] = f2tf32(As[row * 32 + s1]);
                    afr[mb][3] = f2tf32(As[(row + 8) * 32 + s1]);
                } else {
                    afr[mb][0] = __float_as_uint(As[row * 32 + s0]);
                    afr[mb][1] = __float_as_uint(As[(row + 8) * 32 + s0]);
                    afr[mb][2] = __float_as_uint(As[row * 32 + s1]);
                    afr[mb][3] = __float_as_uint(As[(row + 8) * 32 + s1]);
                }
            }
            // B fragments: k-rows s*8+qc and s*8+qc+4; 8 contiguous floats each
            const float4* br0 = (const float4*)&Bs[(s * 8 + qc) * 128 + colb];
            const float4* br1 = (const float4*)&Bs[(s * 8 + qc + 4) * 128 + colb];
            float4 b00 = br0[0], b01 = br0[1];
            float4 b10 = br1[0], b11 = br1[1];
            uint32_t bfr[8][2];
            bfr[0][0] = __float_as_uint(b00.x); bfr[0][1] = __float_as_uint(b10.x);
            bfr[1][0] = __float_as_uint(b00.y); bfr[1][1] = __float_as_uint(b10.y);
            bfr[2][0] = __float_as_uint(b00.z); bfr[2][1] = __float_as_uint(b10.z);
            bfr[3][0] = __float_as_uint(b00.w); bfr[3][1] = __float_as_uint(b10.w);
            bfr[4][0] = __float_as_uint(b01.x); bfr[4][1] = __float_as_uint(b11.x);
            bfr[5][0] = __float_as_uint(b01.y); bfr[5][1] = __float_as_uint(b11.y);
            bfr[6][0] = __float_as_uint(b01.z); bfr[6][1] = __float_as_uint(b11.z);
            bfr[7][0] = __float_as_uint(b01.w); bfr[7][1] = __float_as_uint(b11.w);

            #pragma unroll
            for (int mb = 0; mb < 2; mb++)
                #pragma unroll
                for (int j = 0; j < 8; j++)
                    mma_tf32(acc[mb][j], afr[mb], bfr[j]);
        }
    }

    #pragma unroll
    for (int mb = 0; mb < 2; mb++) {
        int row = bm * 128 + wm * 32 + mb * 16 + qr;
        #pragma unroll
        for (int j = 0; j < 8; j++) {
            int col = bn * 128 + wn * 64 + j * 8 + qc * 2;
            float2 bb = *(const float2*)(bias + col);
            float2 o0 = make_float2(acc[mb][j][0] + bb.x, acc[mb][j][1] + bb.y);
            float2 o1 = make_float2(acc[mb][j][2] + bb.x, acc[mb][j][3] + bb.y);
            *(float2*)(C + (size_t)row * 1024 + col)       = o0;
            *(float2*)(C + (size_t)(row + 8) * 1024 + col) = o1;
        }
    }
}

// ---------------- mean-reduced weights --------------------------------------
__global__ __launch_bounds__(256) void wmean_kernel(
    const float* __restrict__ Wq, const float* __restrict__ Wk,
    float* __restrict__ Wm)
{
    int id = blockIdx.x * 256 + threadIdx.x;
    int t = id >> 14;
    int h = (id >> 10) & 15;
    int d = id & 1023;
    const float* W = t ? Wk : Wq;
    const float4* p = (const float4*)(W + (size_t)d * 1024 + h * 64);
    float s = 0.0f;
    #pragma unroll
    for (int c = 0; c < 16; c++) {
        float4 v = __ldg(&p[c]);
        s += (v.x + v.y) + (v.z + v.w);
    }
    Wm[id] = s * (1.0f / 64.0f);
}

// ---------------- skinny mean-projection ------------------------------------
__global__ __launch_bounds__(256) void qkmean_kernel(
    const float* __restrict__ queries, const float* __restrict__ keys,
    const float* __restrict__ Wm, float* __restrict__ qm, float* __restrict__ km)
{
    extern __shared__ float swm[];
    const int tid = threadIdx.x;
    for (int i = tid * 4; i < 32768; i += 1024)
        *(float4*)(swm + i) = *(const float4*)(Wm + i);
    __syncthreads();

    const int w = tid >> 5, lane = tid & 31;
    const int m0 = blockIdx.x * 32 + w * 4;

    #pragma unroll
    for (int ph = 0; ph < 2; ph++) {
        const float* src = ph ? keys : queries;
        float* dst = ph ? g_km : g_qm;
        const float* base = src + (size_t)m0 * 1024 + lane * 4;
        const float* tw_ = swm + ph * 16384 + lane * 4;

        float acc[4][16];
        #pragma unroll
        for (int r = 0; r < 4; r++)
            #pragma unroll
            for (int h = 0; h < 16; h++) acc[r][h] = 0.0f;

        #pragma unroll
        for (int c = 0; c < 8; c++) {
            float4 x0 = *(const float4*)(base + 0 * 1024 + c * 128);
            float4 x1 = *(const float4*)(base + 1 * 1024 + c * 128);
            float4 x2 = *(const float4*)(base + 2 * 1024 + c * 128);
            float4 x3 = *(const float4*)(base + 3 * 1024 + c * 128);
            #pragma unroll
            for (int h = 0; h < 16; h++) {
                float4 wv = *(const float4*)(tw_ + h * 1024 + c * 128);
                acc[0][h] += x0.x*wv.x + x0.y*wv.y + x0.z*wv.z + x0.w*wv.w;
                acc[1][h] += x1.x*wv.x + x1.y*wv.y + x1.z*wv.z + x1.w*wv.w;
                acc[2][h] += x2.x*wv.x + x2.y*wv.y + x2.z*wv.z + x2.w*wv.w;
                acc[3][h] += x3.x*wv.x + x3.y*wv.y + x3.z*wv.z + x3.w*wv.w;
            }
        }

        #pragma unroll
        for (int r = 0; r < 4; r++) {
            int m = m0 + r;
            int b = m >> 12, l = m & 4095;
            float* out = dst + (((size_t)b * 16) << 12) + l;
            #pragma unroll
            for (int h = 0; h < 16; h++) {
                float v = acc[r][h];
                v += __shfl_xor_sync(0xFFFFFFFFu, v, 16);
                v += __shfl_xor_sync(0xFFFFFFFFu, v, 8);
                v += __shfl_xor_sync(0xFFFFFFFFu, v, 4);
                v += __shfl_xor_sync(0xFFFFFFFFu, v, 2);
                v += __shfl_xor_sync(0xFFFFFFFFu, v, 1);
                if (lane == h) out[(size_t)h << 12] = v;
            }
        }
    }
}

// ---------------- FFT correlation + top-8 + softmax (fused, 512 thr) --------
__global__ __launch_bounds__(512) void fft_corr_top8_kernel(
    const float* __restrict__ qm, const float* __restrict__ km,
    float* __restrict__ w, int* __restrict__ delays)
{
    extern __shared__ float2 fsm[];
    float2* buf0 = fsm;
    float2* buf1 = fsm + 4096;
    float2* tw   = fsm + 8192;
    float*  sc   = (float*)(fsm + 8192);
    __shared__ float svals[512];
    __shared__ int   sidx[512];
    __shared__ float topv[TOPK];
    __shared__ int   topi[TOPK];

    const int bh = blockIdx.x, tid = threadIdx.x;
    const float* q = qm + (size_t)bh * L_;
    const float* k = km + (size_t)bh * L_;
    for (int i = tid; i < 4096; i += 512) buf0[i] = make_float2(q[i], k[i]);
    for (int r = tid; r < 2048; r += 512) {
        float sv, cv;
        __sincosf(-6.2831853071795865f * (float)r / 4096.0f, &sv, &cv);
        tw[r] = make_float2(cv, sv);
    }
    __syncthreads();

    // FFT #1
    {
        float2 *x = buf0, *y = buf1;
        for (int t = 0; t < 12; t++) {
            int s = 1 << t;
            #pragma unroll
            for (int ii = 0; ii < 4; ii++) {
                int idx = tid + ii * 512;
                float2 a = x[idx];
                float2 b = x[idx + 2048];
                int r = idx & ~(s - 1);
                int kl = idx & (s - 1);
                float2 wv = tw[r];
                float dx = a.x - b.x, dy = a.y - b.y;
                y[2 * r + kl]     = make_float2(a.x + b.x, a.y + b.y);
                y[2 * r + kl + s] = make_float2(dx * wv.x - dy * wv.y,
                                                dx * wv.y + dy * wv.x);
            }
            __syncthreads();
            float2* t2 = x; x = y; y = t2;
        }
    }

    // Hermitian split + conj(Q*conj(K)) into buf1
    for (int i = tid; i < 4096; i += 512) {
        float2 zi = buf0[i];
        float2 zn = buf0[(4096 - i) & 4095];
        float qx = 0.5f * (zi.x + zn.x);
        float qy = 0.5f * (zi.y - zn.y);
        float ux = zi.x - zn.x;
        float uy = zi.y + zn.y;
        float kx = 0.5f * uy;
        float ky = -0.5f * ux;
        float px = qx * kx + qy * ky;
        float py = qy * kx - qx * ky;
        buf1[i] = make_float2(px, -py);
    }
    __syncthreads();

    // FFT #2
    {
        float2 *x = buf1, *y = buf0;
        for (int t = 0; t < 12; t++) {
            int s = 1 << t;
            #pragma unroll
            for (int ii = 0; ii < 4; ii++) {
                int idx = tid + ii * 512;
                float2 a = x[idx];
                float2 b = x[idx + 2048];
                int r = idx & ~(s - 1);
                int kl = idx & (s - 1);
                float2 wv = tw[r];
                float dx = a.x - b.x, dy = a.y - b.y;
                y[2 * r + kl]     = make_float2(a.x + b.x, a.y + b.y);
                y[2 * r + kl + s] = make_float2(dx * wv.x - dy * wv.y,
                                                dx * wv.y + dy * wv.x);
            }
            __syncthreads();
            float2* t2 = x; x = y; y = t2;
        }
    }

    for (int i = tid; i < 4096; i += 512)
        sc[i] = buf1[i].x * (1.0f / 4096.0f);
    __syncthreads();

    for (int r = 0; r < TOPK; r++) {
        float best = -INFINITY; int bi = 0;
        for (int i = tid; i < 4096; i += 512) {
            float v = sc[i];
            if (v > best) { best = v; bi = i; }
        }
        svals[tid] = best;
        sidx[tid] = bi;
        __syncthreads();
        for (int s = 256; s > 0; s >>= 1) {
            if (tid < s) {
                float v2 = svals[tid + s];
                int   i2 = sidx[tid + s];
                float v1 = svals[tid];
                int   i1 = sidx[tid];
                if (v2 > v1 || (v2 == v1 && i2 < i1)) {
                    svals[tid] = v2;
                    sidx[tid] = i2;
                }
            }
            __syncthreads();
        }
        if (tid == 0) {
            topv[r] = svals[0];
            topi[r] = sidx[0];
            sc[sidx[0]] = -INFINITY;
        }
        __syncthreads();
    }

    if (tid == 0) {
        float mx = topv[0];
        float e[TOPK], s = 0.0f;
        #pragma unroll
        for (int r = 0; r < TOPK; r++) { e[r] = expf(topv[r] - mx); s += e[r]; }
        float inv = 1.0f / s;
        #pragma unroll
        for (int r = 0; r < TOPK; r++) {
            w[bh * TOPK + r] = e[r] * inv;
            delays[bh * TOPK + r] = topi[r];
        }
    }
}

// ---------------- gather (writes tf32-rounded output) ------------------------
__global__ __launch_bounds__(256) void gather_kernel(
    const float* __restrict__ Vp, const float* __restrict__ w,
    const int* __restrict__ delays, float* __restrict__ out)
{
    unsigned gid = blockIdx.x * blockDim.x + threadIdx.x;
    int d4 = gid & 255;
    int l  = (gid >> 8) & (L_ - 1);
    int b  = gid >> 20;
    int h  = d4 >> 4;
    int bh = b * H_ + h;

    float4 a = make_float4(0.f, 0.f, 0.f, 0.f);
    #pragma unroll
    for (int r = 0; r < TOPK; r++) {
        float wr = __ldg(&w[bh * TOPK + r]);
        int   dl = __ldg(&delays[bh * TOPK + r]);
        int   lm = (l - dl) & (L_ - 1);
        const float4 v = *(const float4*)(Vp + (size_t)(b * L_ + lm) * D_ + d4 * 4);
        a.x += wr * v.x; a.y += wr * v.y; a.z += wr * v.z; a.w += wr * v.w;
    }
    float4 o;
    o.x = __uint_as_float(f2tf32(a.x));
    o.y = __uint_as_float(f2tf32(a.y));
    o.z = __uint_as_float(f2tf32(a.z));
    o.w = __uint_as_float(f2tf32(a.w));
    *(float4*)(out + (size_t)gid * 4) = o;
}

// ---------------- launch ------------------------------------------------------
extern "C" void kernel_launch(void* const* d_in, const int* in_sizes, int n_in,
                              void* d_out, int out_size)
{
    const float* queries = (const float*)d_in[0];
    const float* keys    = (const float*)d_in[1];
    const float* values  = (const float*)d_in[2];
    const float* Wq = (const float*)d_in[3];
    const float* Wk = (const float*)d_in[5];
    const float* Wv = (const float*)d_in[7];
    const float* bv = (const float*)d_in[8];
    const float* Wo = (const float*)d_in[9];
    const float* bo = (const float*)d_in[10];
    float* out = (float*)d_out;

    float *Vp, *pre, *Wvr, *Wor, *qm, *km, *Wm, *w;
    int* delays;
    cudaGetSymbolAddress((void**)&Vp, g_Vp);
    cudaGetSymbolAddress((void**)&pre, g_pre);
    cudaGetSymbolAddress((void**)&Wvr, g_Wvr);
    cudaGetSymbolAddress((void**)&Wor, g_Wor);
    cudaGetSymbolAddress((void**)&qm, g_qm);
    cudaGetSymbolAddress((void**)&km, g_km);
    cudaGetSymbolAddress((void**)&Wm, g_Wm);
    cudaGetSymbolAddress((void**)&w, g_w);
    cudaGetSymbolAddress((void**)&delays, g_delays);

    cudaFuncSetAttribute(gemm_tf32_kernel<true>,
                         cudaFuncAttributeMaxDynamicSharedMemorySize, GEMM_SMEM);
    cudaFuncSetAttribute(gemm_tf32_kernel<false>,
                         cudaFuncAttributeMaxDynamicSharedMemorySize, GEMM_SMEM);
    cudaFuncSetAttribute(qkmean_kernel,
                         cudaFuncAttributeMaxDynamicSharedMemorySize, 131072);
    cudaFuncSetAttribute(fft_corr_top8_kernel,
                         cudaFuncAttributeMaxDynamicSharedMemorySize, 81920);

    dim3 gemm_grid(8, 128);

    wprep_kernel<<<4096, 256>>>(Wv, Wvr);
    wprep_kernel<<<4096, 256>>>(Wo, Wor);

    gemm_tf32_kernel<true><<<gemm_grid, 256, GEMM_SMEM>>>(values, Wvr, bv, Vp);

    wmean_kernel<<<128, 256>>>(Wq, Wk, Wm);
    qkmean_kernel<<<512, 256, 131072>>>(queries, keys, Wm, qm, km);
    fft_corr_top8_kernel<<<BH_, 512, 81920>>>(qm, km, w, delays);

    gather_kernel<<<(M_ * D_ / 4) / 256, 256>>>(Vp, w, delays, pre);

    gemm_tf32_kernel<false><<<gemm_grid, 256, GEMM_SMEM>>>(pre, Wor, bo, out);
}

// round 9
// speedup vs baseline: 1.8508x; 1.0331x over previous
#include <cuda_runtime.h>
#include <cuda_bf16.h>
#include <math.h>
#include <stdint.h>

#define B_   4
#define L_   4096
#define D_   1024
#define H_   16
#define DK_  64
#define BH_  (B_ * H_)
#define TOPK 8
#define M_   (B_ * L_)   // 16384

// ---------------- scratch (device globals; no runtime allocation) ----------
__device__ float g_Vp[M_ * D_];
__device__ float g_pre[M_ * D_];
__device__ float g_Wvr[D_ * D_];        // pre-rounded+permuted Wv
__device__ float g_Wor[D_ * D_];        // pre-rounded+permuted Wo
__device__ float g_qm[BH_ * L_];
__device__ float g_km[BH_ * L_];
__device__ float g_Wm[2 * H_ * D_];
__device__ float g_w[BH_ * TOPK];
__device__ int   g_delays[BH_ * TOPK];

// ---------------- helpers ----------------------------------------------------
__device__ __forceinline__ uint32_t smem_u32(const void* p) {
    uint32_t a;
    asm("{ .reg .u64 t; cvta.to.shared.u64 t, %1; cvt.u32.u64 %0, t; }"
        : "=r"(a) : "l"(p));
    return a;
}
__device__ __forceinline__ void cp16(uint32_t dst, const void* src) {
    asm volatile("cp.async.cg.shared.global [%0], [%1], 16;"
                 :: "r"(dst), "l"(src));
}
__device__ __forceinline__ uint32_t f2tf32(float f) {
    uint32_t u;
    asm("cvt.rna.tf32.f32 %0, %1;" : "=r"(u) : "f"(f));
    return u;
}
__device__ __forceinline__ void mma_tf32(float* d, const uint32_t* a, const uint32_t* b) {
    asm volatile(
        "mma.sync.aligned.m16n8k8.row.col.f32.tf32.tf32.f32 "
        "{%0,%1,%2,%3}, {%4,%5,%6,%7}, {%8,%9}, {%0,%1,%2,%3};"
        : "+f"(d[0]), "+f"(d[1]), "+f"(d[2]), "+f"(d[3])
        : "r"(a[0]), "r"(a[1]), "r"(a[2]), "r"(a[3]), "r"(b[0]), "r"(b[1]));
}

// ---------------- W prep: tf32-round + intra-64 column permutation ----------
__global__ __launch_bounds__(256) void wprep_kernel(
    const float* __restrict__ W, float* __restrict__ Wr)
{
    int id = blockIdx.x * 256 + threadIdx.x;
    int k = id >> 10;
    int c = id & 1023;
    int g = c & ~63;
    int p = c & 63;
    int v = ((p & 7) << 3) + (p >> 3);
    float x = __ldg(&W[(size_t)k * 1024 + g + v]);
    Wr[id] = __uint_as_float(f2tf32(x));
}

// ---------------- tf32 mma GEMM ----------------------------------------------
#define A_ST_F 4096
#define STAGE_F 8192
#define STAGE_BYTES (STAGE_F * 4)
#define GEMM_SMEM (3 * STAGE_BYTES)   // 96 KB

template<bool CVT_A>
__global__ __launch_bounds__(256, 2) void gemm_tf32_kernel(
    const float* __restrict__ A, const float* __restrict__ W,
    const float* __restrict__ bias, float* __restrict__ C)
{
    extern __shared__ float sm[];
    const uint32_t su = smem_u32(sm);
    const int tid = threadIdx.x;
    const int bn = blockIdx.x;
    const int bm = blockIdx.y;
    const int wid = tid >> 5, lane = tid & 31;
    const int wm = wid >> 1, wn = wid & 1;
    const int qr = lane >> 2, qc = lane & 3;

    const float* Ab = A + (size_t)(bm * 128 + (tid >> 3)) * 1024 + (tid & 7) * 4;
    const float* Wb = W + (size_t)(tid >> 5) * 1024 + bn * 128 + (tid & 31) * 4;

    uint32_t saoff[4], sboff[4];
    #pragma unroll
    for (int p = 0; p < 4; p++) {
        int row = (tid >> 3) + p * 32;
        saoff[p] = (row * 32 + (((tid & 7) ^ (row & 7)) << 2)) * 4;
        int k = (tid >> 5) + p * 8;
        sboff[p] = (A_ST_F + k * 128 + (((tid & 31) << 2) ^ ((k & 3) << 3))) * 4;
    }

    float acc[2][8][4];
    #pragma unroll
    for (int mb = 0; mb < 2; mb++)
        #pragma unroll
        for (int j = 0; j < 8; j++)
            #pragma unroll
            for (int v = 0; v < 4; v++) acc[mb][j][v] = 0.0f;

    auto load_stage = [&](int st, int kt) {
        uint32_t base = su + st * STAGE_BYTES;
        #pragma unroll
        for (int p = 0; p < 4; p++) {
            cp16(base + saoff[p], Ab + kt * 32 + p * 32 * 1024);
            cp16(base + sboff[p], Wb + (size_t)(kt * 32 + p * 8) * 1024);
        }
    };

    load_stage(0, 0);
    asm volatile("cp.async.commit_group;");
    load_stage(1, 1);
    asm volatile("cp.async.commit_group;");

    const int rowa0 = wm * 32 + qr;
    const int colb = (wn * 64 + qr * 8) ^ (qc << 3);

    for (int kt = 0; kt < 32; kt++) {
        const int st = kt % 3;
        if (kt < 30) asm volatile("cp.async.wait_group 1;");
        else         asm volatile("cp.async.wait_group 0;");
        __syncthreads();
        if (kt < 30) {
            load_stage((kt + 2) % 3, kt + 2);
            asm volatile("cp.async.commit_group;");
        }

        const float* As = sm + st * STAGE_F;
        const float* Bs = As + A_ST_F;

        #pragma unroll
        for (int s = 0; s < 4; s++) {
            uint32_t afr[2][4];
            #pragma unroll
            for (int mb = 0; mb < 2; mb++) {
                int row = rowa0 + mb * 16;
                int s0 = (((s * 2)     ^ qr) << 2) + qc;
                int s1 = (((s * 2 + 1) ^ qr) << 2) + qc;
                if (CVT_A) {
                    afr[mb][0] = f2tf32(As[row * 32 + s0]);
                    afr[mb][1] = f2tf32(As[(row + 8) * 32 + s0]);
                    afr[mb][2] = f2tf32(As[row * 32 + s1]);
                    afr[mb][3] = f2tf32(As[(row + 8) * 32 + s1]);
                } else {
                    afr[mb][0] = __float_as_uint(As[row * 32 + s0]);
                    afr[mb][1] = __float_as_uint(As[(row + 8) * 32 + s0]);
                    afr[mb][2] = __float_as_uint(As[row * 32 + s1]);
                    afr[mb][3] = __float_as_uint(As[(row + 8) * 32 + s1]);
                }
            }
            const float4* br0 = (const float4*)&Bs[(s * 8 + qc) * 128 + colb];
            const float4* br1 = (const float4*)&Bs[(s * 8 + qc + 4) * 128 + colb];
            float4 b00 = br0[0], b01 = br0[1];
            float4 b10 = br1[0], b11 = br1[1];
            uint32_t bfr[8][2];
            bfr[0][0] = __float_as_uint(b00.x); bfr[0][1] = __float_as_uint(b10.x);
            bfr[1][0] = __float_as_uint(b00.y); bfr[1][1] = __float_as_uint(b10.y);
            bfr[2][0] = __float_as_uint(b00.z); bfr[2][1] = __float_as_uint(b10.z);
            bfr[3][0] = __float_as_uint(b00.w); bfr[3][1] = __float_as_uint(b10.w);
            bfr[4][0] = __float_as_uint(b01.x); bfr[4][1] = __float_as_uint(b11.x);
            bfr[5][0] = __float_as_uint(b01.y); bfr[5][1] = __float_as_uint(b11.y);
            bfr[6][0] = __float_as_uint(b01.z); bfr[6][1] = __float_as_uint(b11.z);
            bfr[7][0] = __float_as_uint(b01.w); bfr[7][1] = __float_as_uint(b11.w);

            #pragma unroll
            for (int mb = 0; mb < 2; mb++)
                #pragma unroll
                for (int j = 0; j < 8; j++)
                    mma_tf32(acc[mb][j], afr[mb], bfr[j]);
        }
    }

    #pragma unroll
    for (int mb = 0; mb < 2; mb++) {
        int row = bm * 128 + wm * 32 + mb * 16 + qr;
        #pragma unroll
        for (int j = 0; j < 8; j++) {
            int col = bn * 128 + wn * 64 + j * 8 + qc * 2;
            float2 bb = *(const float2*)(bias + col);
            float2 o0 = make_float2(acc[mb][j][0] + bb.x, acc[mb][j][1] + bb.y);
            float2 o1 = make_float2(acc[mb][j][2] + bb.x, acc[mb][j][3] + bb.y);
            *(float2*)(C + (size_t)row * 1024 + col)       = o0;
            *(float2*)(C + (size_t)(row + 8) * 1024 + col) = o1;
        }
    }
}

// ---------------- mean-reduced weights --------------------------------------
__global__ __launch_bounds__(256) void wmean_kernel(
    const float* __restrict__ Wq, const float* __restrict__ Wk,
    float* __restrict__ Wm)
{
    int id = blockIdx.x * 256 + threadIdx.x;
    int t = id >> 14;
    int h = (id >> 10) & 15;
    int d = id & 1023;
    const float* W = t ? Wk : Wq;
    const float4* p = (const float4*)(W + (size_t)d * 1024 + h * 64);
    float s = 0.0f;
    #pragma unroll
    for (int c = 0; c < 16; c++) {
        float4 v = __ldg(&p[c]);
        s += (v.x + v.y) + (v.z + v.w);
    }
    Wm[id] = s * (1.0f / 64.0f);
}

// ---------------- skinny mean-projection ------------------------------------
__global__ __launch_bounds__(256) void qkmean_kernel(
    const float* __restrict__ queries, const float* __restrict__ keys,
    const float* __restrict__ Wm, float* __restrict__ qm, float* __restrict__ km)
{
    extern __shared__ float swm[];
    const int tid = threadIdx.x;
    for (int i = tid * 4; i < 32768; i += 1024)
        *(float4*)(swm + i) = *(const float4*)(Wm + i);
    __syncthreads();

    const int w = tid >> 5, lane = tid & 31;
    const int m0 = blockIdx.x * 32 + w * 4;

    #pragma unroll
    for (int ph = 0; ph < 2; ph++) {
        const float* src = ph ? keys : queries;
        float* dst = ph ? g_km : g_qm;
        const float* base = src + (size_t)m0 * 1024 + lane * 4;
        const float* tw_ = swm + ph * 16384 + lane * 4;

        float acc[4][16];
        #pragma unroll
        for (int r = 0; r < 4; r++)
            #pragma unroll
            for (int h = 0; h < 16; h++) acc[r][h] = 0.0f;

        #pragma unroll
        for (int c = 0; c < 8; c++) {
            float4 x0 = *(const float4*)(base + 0 * 1024 + c * 128);
            float4 x1 = *(const float4*)(base + 1 * 1024 + c * 128);
            float4 x2 = *(const float4*)(base + 2 * 1024 + c * 128);
            float4 x3 = *(const float4*)(base + 3 * 1024 + c * 128);
            #pragma unroll
            for (int h = 0; h < 16; h++) {
                float4 wv = *(const float4*)(tw_ + h * 1024 + c * 128);
                acc[0][h] += x0.x*wv.x + x0.y*wv.y + x0.z*wv.z + x0.w*wv.w;
                acc[1][h] += x1.x*wv.x + x1.y*wv.y + x1.z*wv.z + x1.w*wv.w;
                acc[2][h] += x2.x*wv.x + x2.y*wv.y + x2.z*wv.z + x2.w*wv.w;
                acc[3][h] += x3.x*wv.x + x3.y*wv.y + x3.z*wv.z + x3.w*wv.w;
            }
        }

        #pragma unroll
        for (int r = 0; r < 4; r++) {
            int m = m0 + r;
            int b = m >> 12, l = m & 4095;
            float* out = dst + (((size_t)b * 16) << 12) + l;
            #pragma unroll
            for (int h = 0; h < 16; h++) {
                float v = acc[r][h];
                v += __shfl_xor_sync(0xFFFFFFFFu, v, 16);
                v += __shfl_xor_sync(0xFFFFFFFFu, v, 8);
                v += __shfl_xor_sync(0xFFFFFFFFu, v, 4);
                v += __shfl_xor_sync(0xFFFFFFFFu, v, 2);
                v += __shfl_xor_sync(0xFFFFFFFFu, v, 1);
                if (lane == h) out[(size_t)h << 12] = v;
            }
        }
    }
}

// ---------------- FFT correlation + top-8 + softmax (fused, 512 thr) --------
__global__ __launch_bounds__(512) void fft_corr_top8_kernel(
    const float* __restrict__ qm, const float* __restrict__ km,
    float* __restrict__ w, int* __restrict__ delays)
{
    extern __shared__ float2 fsm[];
    float2* buf0 = fsm;
    float2* buf1 = fsm + 4096;
    float2* tw   = fsm + 8192;
    float*  sc   = (float*)(fsm + 8192);
    __shared__ float svals[512];
    __shared__ int   sidx[512];
    __shared__ float topv[TOPK];
    __shared__ int   topi[TOPK];

    const int bh = blockIdx.x, tid = threadIdx.x;
    const float* q = qm + (size_t)bh * L_;
    const float* k = km + (size_t)bh * L_;
    for (int i = tid; i < 4096; i += 512) buf0[i] = make_float2(q[i], k[i]);
    for (int r = tid; r < 2048; r += 512) {
        float sv, cv;
        __sincosf(-6.2831853071795865f * (float)r / 4096.0f, &sv, &cv);
        tw[r] = make_float2(cv, sv);
    }
    __syncthreads();

    // FFT #1
    {
        float2 *x = buf0, *y = buf1;
        for (int t = 0; t < 12; t++) {
            int s = 1 << t;
            #pragma unroll
            for (int ii = 0; ii < 4; ii++) {
                int idx = tid + ii * 512;
                float2 a = x[idx];
                float2 b = x[idx + 2048];
                int r = idx & ~(s - 1);
                int kl = idx & (s - 1);
                float2 wv = tw[r];
                float dx = a.x - b.x, dy = a.y - b.y;
                y[2 * r + kl]     = make_float2(a.x + b.x, a.y + b.y);
                y[2 * r + kl + s] = make_float2(dx * wv.x - dy * wv.y,
                                                dx * wv.y + dy * wv.x);
            }
            __syncthreads();
            float2* t2 = x; x = y; y = t2;
        }
    }

    // Hermitian split + conj(Q*conj(K)) into buf1
    for (int i = tid; i < 4096; i += 512) {
        float2 zi = buf0[i];
        float2 zn = buf0[(4096 - i) & 4095];
        float qx = 0.5f * (zi.x + zn.x);
        float qy = 0.5f * (zi.y - zn.y);
        float ux = zi.x - zn.x;
        float uy = zi.y + zn.y;
        float kx = 0.5f * uy;
        float ky = -0.5f * ux;
        float px = qx * kx + qy * ky;
        float py = qy * kx - qx * ky;
        buf1[i] = make_float2(px, -py);
    }
    __syncthreads();

    // FFT #2
    {
        float2 *x = buf1, *y = buf0;
        for (int t = 0; t < 12; t++) {
            int s = 1 << t;
            #pragma unroll
            for (int ii = 0; ii < 4; ii++) {
                int idx = tid + ii * 512;
                float2 a = x[idx];
                float2 b = x[idx + 2048];
                int r = idx & ~(s - 1);
                int kl = idx & (s - 1);
                float2 wv = tw[r];
                float dx = a.x - b.x, dy = a.y - b.y;
                y[2 * r + kl]     = make_float2(a.x + b.x, a.y + b.y);
                y[2 * r + kl + s] = make_float2(dx * wv.x - dy * wv.y,
                                                dx * wv.y + dy * wv.x);
            }
            __syncthreads();
            float2* t2 = x; x = y; y = t2;
        }
    }

    for (int i = tid; i < 4096; i += 512)
        sc[i] = buf1[i].x * (1.0f / 4096.0f);
    __syncthreads();

    for (int r = 0; r < TOPK; r++) {
        float best = -INFINITY; int bi = 0;
        for (int i = tid; i < 4096; i += 512) {
            float v = sc[i];
            if (v > best) { best = v; bi = i; }
        }
        svals[tid] = best;
        sidx[tid] = bi;
        __syncthreads();
        for (int s = 256; s > 0; s >>= 1) {
            if (tid < s) {
                float v2 = svals[tid + s];
                int   i2 = sidx[tid + s];
                float v1 = svals[tid];
                int   i1 = sidx[tid];
                if (v2 > v1 || (v2 == v1 && i2 < i1)) {
                    svals[tid] = v2;
                    sidx[tid] = i2;
                }
            }
            __syncthreads();
        }
        if (tid == 0) {
            topv[r] = svals[0];
            topi[r] = sidx[0];
            sc[sidx[0]] = -INFINITY;
        }
        __syncthreads();
    }

    if (tid == 0) {
        float mx = topv[0];
        float e[TOPK], s = 0.0f;
        #pragma unroll
        for (int r = 0; r < TOPK; r++) { e[r] = expf(topv[r] - mx); s += e[r]; }
        float inv = 1.0f / s;
        #pragma unroll
        for (int r = 0; r < TOPK; r++) {
            w[bh * TOPK + r] = e[r] * inv;
            delays[bh * TOPK + r] = topi[r];
        }
    }
}

// ---------------- gather (writes tf32-rounded output) ------------------------
__global__ __launch_bounds__(256) void gather_kernel(
    const float* __restrict__ Vp, const float* __restrict__ w,
    const int* __restrict__ delays, float* __restrict__ out)
{
    unsigned gid = blockIdx.x * blockDim.x + threadIdx.x;
    int d4 = gid & 255;
    int l  = (gid >> 8) & (L_ - 1);
    int b  = gid >> 20;
    int h  = d4 >> 4;
    int bh = b * H_ + h;

    float4 a = make_float4(0.f, 0.f, 0.f, 0.f);
    #pragma unroll
    for (int r = 0; r < TOPK; r++) {
        float wr = __ldg(&w[bh * TOPK + r]);
        int   dl = __ldg(&delays[bh * TOPK + r]);
        int   lm = (l - dl) & (L_ - 1);
        const float4 v = *(const float4*)(Vp + (size_t)(b * L_ + lm) * D_ + d4 * 4);
        a.x += wr * v.x; a.y += wr * v.y; a.z += wr * v.z; a.w += wr * v.w;
    }
    float4 o;
    o.x = __uint_as_float(f2tf32(a.x));
    o.y = __uint_as_float(f2tf32(a.y));
    o.z = __uint_as_float(f2tf32(a.z));
    o.w = __uint_as_float(f2tf32(a.w));
    *(float4*)(out + (size_t)gid * 4) = o;
}

// ---------------- launch ------------------------------------------------------
extern "C" void kernel_launch(void* const* d_in, const int* in_sizes, int n_in,
                              void* d_out, int out_size)
{
    const float* queries = (const float*)d_in[0];
    const float* keys    = (const float*)d_in[1];
    const float* values  = (const float*)d_in[2];
    const float* Wq = (const float*)d_in[3];
    const float* Wk = (const float*)d_in[5];
    const float* Wv = (const float*)d_in[7];
    const float* bv = (const float*)d_in[8];
    const float* Wo = (const float*)d_in[9];
    const float* bo = (const float*)d_in[10];
    float* out = (float*)d_out;

    float *Vp, *pre, *Wvr, *Wor, *qm, *km, *Wm, *w;
    int* delays;
    cudaGetSymbolAddress((void**)&Vp, g_Vp);
    cudaGetSymbolAddress((void**)&pre, g_pre);
    cudaGetSymbolAddress((void**)&Wvr, g_Wvr);
    cudaGetSymbolAddress((void**)&Wor, g_Wor);
    cudaGetSymbolAddress((void**)&qm, g_qm);
    cudaGetSymbolAddress((void**)&km, g_km);
    cudaGetSymbolAddress((void**)&Wm, g_Wm);
    cudaGetSymbolAddress((void**)&w, g_w);
    cudaGetSymbolAddress((void**)&delays, g_delays);

    cudaFuncSetAttribute(gemm_tf32_kernel<true>,
                         cudaFuncAttributeMaxDynamicSharedMemorySize, GEMM_SMEM);
    cudaFuncSetAttribute(gemm_tf32_kernel<false>,
                         cudaFuncAttributeMaxDynamicSharedMemorySize, GEMM_SMEM);
    cudaFuncSetAttribute(qkmean_kernel,
                         cudaFuncAttributeMaxDynamicSharedMemorySize, 131072);
    cudaFuncSetAttribute(fft_corr_top8_kernel,
                         cudaFuncAttributeMaxDynamicSharedMemorySize, 81920);

    dim3 gemm_grid(8, 128);

    // fork-join: the qk-mean/FFT chain + Wo prep depend only on inputs, so run
    // them on a side stream concurrent with the V projection GEMM.
    // (host-side handles only; created per call, never destroyed mid-capture)
    cudaStream_t side;
    cudaEvent_t evFork, evJoin;
    cudaStreamCreateWithFlags(&side, cudaStreamNonBlocking);
    cudaEventCreateWithFlags(&evFork, cudaEventDisableTiming);
    cudaEventCreateWithFlags(&evJoin, cudaEventDisableTiming);

    cudaEventRecord(evFork, 0);
    cudaStreamWaitEvent(side, evFork, 0);

    // main stream: V projection (critical path)
    wprep_kernel<<<4096, 256>>>(Wv, Wvr);
    gemm_tf32_kernel<true><<<gemm_grid, 256, GEMM_SMEM>>>(values, Wvr, bv, Vp);

    // side stream: mean path + Wo prep (hidden under V-GEMM)
    wprep_kernel<<<4096, 256, 0, side>>>(Wo, Wor);
    wmean_kernel<<<128, 256, 0, side>>>(Wq, Wk, Wm);
    qkmean_kernel<<<512, 256, 131072, side>>>(queries, keys, Wm, qm, km);
    fft_corr_top8_kernel<<<BH_, 512, 81920, side>>>(qm, km, w, delays);
    cudaEventRecord(evJoin, side);

    // join, then gather + output projection
    cudaStreamWaitEvent(0, evJoin, 0);
    gather_kernel<<<(M_ * D_ / 4) / 256, 256>>>(Vp, w, delays, pre);
    gemm_tf32_kernel<false><<<gemm_grid, 256, GEMM_SMEM>>>(pre, Wor, bo, out);
}